// round 1
// baseline (speedup 1.0000x reference)
#include <cuda_runtime.h>
#include <cuda_bf16.h>

// GCN: out = relu(adj@(relu(adj@(relu(adj@(x@W1)+b1)@W2)+b2)@W3)+b3)@Wf + bf
// All fp32. N=10000, NFEAT=512, NHID=512, NCLASS=151.
//
// Round 0: correctness baseline. Single generic tiled SGEMM (BM=BN=128, BK=16,
// 8x8 microtile, 256 thr) with fused bias+relu epilogue, launched 7x.
// Scratch via __device__ globals (no allocations; graph-capturable).

#define N_NODES 10000
#define BM 128
#define BN 128
#define BK 16
#define TM 8
#define TN 8
#define NTHREADS 256

// Ping-pong activation buffers (max 10000 x 1024 fp32 each)
__device__ float g_bufA[(size_t)N_NODES * 1024];
__device__ float g_bufB[(size_t)N_NODES * 1024];

// C[M,N] = A[M,K] @ B[K,N]  (+ bias, + relu), all row-major.
template <int DO_RELU, int DO_BIAS>
__global__ void __launch_bounds__(NTHREADS, 2)
sgemm_kernel(const float* __restrict__ A, const float* __restrict__ B,
             const float* __restrict__ bias, float* __restrict__ C,
             int M, int N, int K) {
    // A tile stored row-major [BM][BK+1] (pad kills bank conflicts on the
    // strided inner-loop reads; stores are near-linear).
    __shared__ float As[BM][BK + 1];
    __shared__ float Bs[BK][BN];

    const int tid = threadIdx.x;
    const int tr = tid / (BN / TN);  // 0..15  (row group)
    const int tc = tid % (BN / TN);  // 0..15  (col group)

    const int rowBase = blockIdx.y * BM;
    const int colBase = blockIdx.x * BN;

    float acc[TM][TN];
#pragma unroll
    for (int i = 0; i < TM; i++)
#pragma unroll
        for (int j = 0; j < TN; j++) acc[i][j] = 0.0f;

    for (int k0 = 0; k0 < K; k0 += BK) {
        // ---- load A tile: BM x BK = 2048 elems, 8 per thread ----
#pragma unroll
        for (int i = 0; i < 8; i++) {
            int lin = tid + i * NTHREADS;
            int m = lin >> 4;        // /BK
            int kk = lin & (BK - 1); // %BK
            int gm = rowBase + m;
            int gk = k0 + kk;
            float v = 0.0f;
            if (gm < M && gk < K) v = A[(long)gm * K + gk];
            As[m][kk] = v;
        }
        // ---- load B tile: BK x BN = 2048 elems, 8 per thread ----
#pragma unroll
        for (int i = 0; i < 8; i++) {
            int lin = tid + i * NTHREADS;
            int kk = lin >> 7;        // /BN
            int n = lin & (BN - 1);   // %BN
            int gk = k0 + kk;
            int gn = colBase + n;
            float v = 0.0f;
            if (gk < K && gn < N) v = B[(long)gk * N + gn];
            Bs[kk][n] = v;
        }
        __syncthreads();

#pragma unroll
        for (int kk = 0; kk < BK; kk++) {
            float ra[TM], rb[TN];
#pragma unroll
            for (int i = 0; i < TM; i++) ra[i] = As[tr * TM + i][kk];
#pragma unroll
            for (int j = 0; j < TN; j++) rb[j] = Bs[kk][tc * TN + j];
#pragma unroll
            for (int i = 0; i < TM; i++)
#pragma unroll
                for (int j = 0; j < TN; j++) acc[i][j] += ra[i] * rb[j];
        }
        __syncthreads();
    }

    // ---- epilogue ----
#pragma unroll
    for (int i = 0; i < TM; i++) {
        int gm = rowBase + tr * TM + i;
        if (gm >= M) continue;
#pragma unroll
        for (int j = 0; j < TN; j++) {
            int gn = colBase + tc * TN + j;
            if (gn >= N) continue;
            float v = acc[i][j];
            if (DO_BIAS) v += bias[gn];
            if (DO_RELU) v = fmaxf(v, 0.0f);
            C[(long)gm * N + gn] = v;
        }
    }
}

static inline dim3 make_grid(int M, int N) {
    return dim3((unsigned)((N + BN - 1) / BN), (unsigned)((M + BM - 1) / BM), 1);
}

extern "C" void kernel_launch(void* const* d_in, const int* in_sizes, int n_in,
                              void* d_out, int out_size) {
    const float* x   = (const float*)d_in[0];  // 10000 x 512
    const float* adj = (const float*)d_in[1];  // 10000 x 10000
    const float* W1  = (const float*)d_in[2];  // 512 x 512
    const float* b1  = (const float*)d_in[3];  // 512
    const float* W2  = (const float*)d_in[4];  // 512 x 512
    const float* b2  = (const float*)d_in[5];  // 512
    const float* W3  = (const float*)d_in[6];  // 512 x 1024
    const float* b3  = (const float*)d_in[7];  // 1024
    const float* Wf  = (const float*)d_in[8];  // 1024 x 151
    const float* bf  = (const float*)d_in[9];  // 151
    float* out = (float*)d_out;                // 10000 x 151

    float* bufA = nullptr;
    float* bufB = nullptr;
    cudaGetSymbolAddress((void**)&bufA, g_bufA);
    cudaGetSymbolAddress((void**)&bufB, g_bufB);

    const dim3 blk(NTHREADS);
    const int M = N_NODES;

    // 1: bufA = x @ W1                       [10000,512]
    sgemm_kernel<0, 0><<<make_grid(M, 512), blk>>>(x, W1, nullptr, bufA, M, 512, 512);
    // 2: bufB = relu(adj @ bufA + b1)        [10000,512]
    sgemm_kernel<1, 1><<<make_grid(M, 512), blk>>>(adj, bufA, b1, bufB, M, 512, M);
    // 3: bufA = bufB @ W2                    [10000,512]
    sgemm_kernel<0, 0><<<make_grid(M, 512), blk>>>(bufB, W2, nullptr, bufA, M, 512, 512);
    // 4: bufB = relu(adj @ bufA + b2)        [10000,512]
    sgemm_kernel<1, 1><<<make_grid(M, 512), blk>>>(adj, bufA, b2, bufB, M, 512, M);
    // 5: bufA = bufB @ W3                    [10000,1024]
    sgemm_kernel<0, 0><<<make_grid(M, 1024), blk>>>(bufB, W3, nullptr, bufA, M, 1024, 512);
    // 6: bufB = relu(adj @ bufA + b3)        [10000,1024]
    sgemm_kernel<1, 1><<<make_grid(M, 1024), blk>>>(adj, bufA, b3, bufB, M, 1024, M);
    // 7: out = bufB @ Wf + bf                [10000,151]
    sgemm_kernel<0, 1><<<make_grid(M, 151), blk>>>(bufB, Wf, bf, out, M, 151, 1024);
}

// round 3
// speedup vs baseline: 9.4520x; 9.4520x over previous
#include <cuda_runtime.h>
#include <cstdint>

// GCN via arch-stable tensor-core path: mma.sync tf32 + ldmatrix + cp.async.
// (tcgen05 is sm_103a-gated; harness compiles for base sm_103 target.)
// CTA tile 128x128, BK=32, 4 warps (64x64 warp tile), 3-stage cp.async
// pipeline, SW128 swizzle, fp32 accumulate. Inputs pre-rounded to tf32 (RNA).

#define NNODES 10000
#define KT 32
#define STAGE_BYTES 32768           // A 16KB + B 16KB
#define SMEM_TOTAL (3 * STAGE_BYTES)

__device__ float g_bufA[(size_t)NNODES * 1024];
__device__ float g_bufB[(size_t)NNODES * 1024];
__device__ float g_adjr[(size_t)NNODES * (size_t)NNODES];
__device__ float g_wts[1310720];
#define O_W1T 0
#define O_W2T 262144
#define O_W3T 524288
#define O_WFT 1048576

__device__ __forceinline__ uint32_t smem_u32(const void* p) {
    uint32_t a;
    asm("{ .reg .u64 t; cvta.to.shared.u64 t, %1; cvt.u32.u64 %0, t; }"
        : "=r"(a) : "l"(p));
    return a;
}
// round-to-nearest tf32 (add half-ulp, mask low 13 bits)
__device__ __forceinline__ float rtf32(float v) {
    return __uint_as_float((__float_as_uint(v) + 0x1000u) & 0xFFFFE000u);
}

__device__ __forceinline__ void cpa16(uint32_t dst, const float* src, int bytes) {
    asm volatile("cp.async.cg.shared.global [%0], [%1], 16, %2;"
                 :: "r"(dst), "l"(src), "r"(bytes) : "memory");
}
#define CP_COMMIT() asm volatile("cp.async.commit_group;" ::: "memory")
#define CP_WAIT1()  asm volatile("cp.async.wait_group 1;" ::: "memory")
#define CP_WAIT0()  asm volatile("cp.async.wait_group 0;" ::: "memory")

__device__ __forceinline__ void ldsm4(uint32_t* r, uint32_t a) {
    asm volatile("ldmatrix.sync.aligned.m8n8.x4.shared.b16 {%0,%1,%2,%3}, [%4];"
                 : "=r"(r[0]), "=r"(r[1]), "=r"(r[2]), "=r"(r[3]) : "r"(a));
}
__device__ __forceinline__ void ldsm2(uint32_t* r, uint32_t a) {
    asm volatile("ldmatrix.sync.aligned.m8n8.x2.shared.b16 {%0,%1}, [%2];"
                 : "=r"(r[0]), "=r"(r[1]) : "r"(a));
}
__device__ __forceinline__ void mma8(float* c, const uint32_t* a, const uint32_t* b) {
    asm volatile("mma.sync.aligned.m16n8k8.row.col.f32.tf32.tf32.f32 "
                 "{%0,%1,%2,%3}, {%4,%5,%6,%7}, {%8,%9}, {%0,%1,%2,%3};"
                 : "+f"(c[0]), "+f"(c[1]), "+f"(c[2]), "+f"(c[3])
                 : "r"(a[0]), "r"(a[1]), "r"(a[2]), "r"(a[3]),
                   "r"(b[0]), "r"(b[1]));
}

// C = A[M,K] @ B_nk[N,K]^T ; A,B row-major with leading dim K.
// TRANS: write C^T [N,M]; else C [M,N]. Optional bias/relu/tf32-round.
template <int TRANS, int BIAS, int RELU, int ROUND>
__global__ void __launch_bounds__(128)
tc_gemm(const float* __restrict__ A, const float* __restrict__ B,
        const float* __restrict__ bias, float* __restrict__ C,
        int M, int N, int K) {
    extern __shared__ char smem[];
    const uint32_t sb = smem_u32(smem);
    const int tid = threadIdx.x;
    const int lane = tid & 31, w = tid >> 5;
    const int warp_m = (w & 1) * 64, warp_n = (w >> 1) * 64;
    const int rowBase = blockIdx.y * 128, colBase = blockIdx.x * 128;

    // ---- loader setup: 8 A-chunks + 8 B-chunks (16B each) per thread/stage
    const float* aptr[8]; uint32_t adst[8]; int acol4[8]; bool aval[8];
    const float* bptr[8]; uint32_t bdst[8]; int bcol4[8]; bool bval[8];
#pragma unroll
    for (int i = 0; i < 8; i++) {
        int c = tid + i * 128;
        int r = c >> 3, cc = c & 7;
        adst[i] = (uint32_t)(r * 128 + ((cc ^ (r & 7)) * 16));
        acol4[i] = cc * 4;
        aval[i] = (rowBase + r) < M;
        aptr[i] = aval[i] ? (A + (size_t)(rowBase + r) * K + acol4[i]) : A;
        bdst[i] = adst[i] + 16384;
        bcol4[i] = cc * 4;
        bval[i] = (colBase + r) < N;
        bptr[i] = bval[i] ? (B + (size_t)(colBase + r) * K + bcol4[i]) : B;
    }

    const int nc = (K + KT - 1) / KT;

    auto issue = [&](int c) {
        uint32_t st = sb + (uint32_t)(c % 3) * STAGE_BYTES;
        int k0 = c * KT;
#pragma unroll
        for (int i = 0; i < 8; i++) {
            int nb = (aval[i] && (k0 + acol4[i]) < K) ? 16 : 0;
            cpa16(st + adst[i], nb ? (aptr[i] + k0) : A, nb);
        }
#pragma unroll
        for (int i = 0; i < 8; i++) {
            int nb = (bval[i] && (k0 + bcol4[i]) < K) ? 16 : 0;
            cpa16(st + bdst[i], nb ? (bptr[i] + k0) : B, nb);
        }
        CP_COMMIT();
    };

    issue(0);
    issue(1);

    // ---- fragment load addressing (SW128 swizzle, ldmatrix) ----
    const int l8 = lane & 7;
    const int l16 = lane & 15;
    const uint32_t aLdRow = (uint32_t)(warp_m + l8 + ((lane >> 3) & 1) * 8) * 128;
    const uint32_t bLdRow = (uint32_t)(warp_n + (l16 & 7)) * 128;
    uint32_t aChunk[4], bChunk[4];
#pragma unroll
    for (int s = 0; s < 4; s++) {
        aChunk[s] = (uint32_t)(((s * 2 + (lane >> 4)) ^ l8) * 16);
        bChunk[s] = (uint32_t)(((s * 2 + (l16 >> 3)) ^ (l16 & 7)) * 16);
    }

    float cr[4][8][4];
#pragma unroll
    for (int mt = 0; mt < 4; mt++)
#pragma unroll
        for (int nt = 0; nt < 8; nt++)
#pragma unroll
            for (int r = 0; r < 4; r++) cr[mt][nt][r] = 0.f;

    for (int c = 0; c < nc; c++) {
        CP_WAIT1();
        __syncthreads();
        if (c + 2 < nc) issue(c + 2); else CP_COMMIT();

        const uint32_t sA = sb + (uint32_t)(c % 3) * STAGE_BYTES;
        const uint32_t sB = sA + 16384;
#pragma unroll
        for (int s = 0; s < 4; s++) {
            uint32_t a[4][4], b[8][2];
#pragma unroll
            for (int mt = 0; mt < 4; mt++)
                ldsm4(a[mt], sA + aLdRow + mt * 2048 + aChunk[s]);
#pragma unroll
            for (int nt = 0; nt < 8; nt++)
                ldsm2(b[nt], sB + bLdRow + nt * 1024 + bChunk[s]);
#pragma unroll
            for (int mt = 0; mt < 4; mt++)
#pragma unroll
                for (int nt = 0; nt < 8; nt++)
                    mma8(cr[mt][nt], a[mt], b[nt]);
        }
    }
    CP_WAIT0();

    // ---- epilogue ----
    const int g = lane >> 2, t = lane & 3;
#pragma unroll
    for (int mt = 0; mt < 4; mt++) {
        const int m0 = rowBase + warp_m + mt * 16 + g;
#pragma unroll
        for (int nt = 0; nt < 8; nt++) {
            const int n0 = colBase + warp_n + nt * 8 + 2 * t;
            float v0 = cr[mt][nt][0], v1 = cr[mt][nt][1];
            float v2 = cr[mt][nt][2], v3 = cr[mt][nt][3];
            if (BIAS) {
                float bb0 = (n0 < N) ? bias[n0] : 0.f;
                float bb1 = (n0 + 1 < N) ? bias[n0 + 1] : 0.f;
                v0 += bb0; v1 += bb1; v2 += bb0; v3 += bb1;
            }
            if (RELU) {
                v0 = fmaxf(v0, 0.f); v1 = fmaxf(v1, 0.f);
                v2 = fmaxf(v2, 0.f); v3 = fmaxf(v3, 0.f);
            }
            if (ROUND) {
                v0 = rtf32(v0); v1 = rtf32(v1);
                v2 = rtf32(v2); v3 = rtf32(v3);
            }
            if (TRANS) {
                if (n0 < N) {
                    if (m0 < M)     C[(size_t)n0 * M + m0] = v0;
                    if (m0 + 8 < M) C[(size_t)n0 * M + m0 + 8] = v2;
                }
                if (n0 + 1 < N) {
                    if (m0 < M)     C[(size_t)(n0 + 1) * M + m0] = v1;
                    if (m0 + 8 < M) C[(size_t)(n0 + 1) * M + m0 + 8] = v3;
                }
            } else {
                if (m0 < M) {
                    if (n0 < N)     C[(size_t)m0 * N + n0] = v0;
                    if (n0 + 1 < N) C[(size_t)m0 * N + n0 + 1] = v1;
                }
                if (m0 + 8 < M) {
                    if (n0 < N)     C[(size_t)(m0 + 8) * N + n0] = v2;
                    if (n0 + 1 < N) C[(size_t)(m0 + 8) * N + n0 + 1] = v3;
                }
            }
        }
    }
}

// ---------------- prep kernels ---------------------------------------------
__global__ void round_copy_kernel(const float4* __restrict__ in,
                                  float4* __restrict__ out, int nquads) {
    int i = blockIdx.x * blockDim.x + threadIdx.x;
    int stride = gridDim.x * blockDim.x;
    for (; i < nquads; i += stride) {
        float4 v = in[i];
        v.x = rtf32(v.x); v.y = rtf32(v.y); v.z = rtf32(v.z); v.w = rtf32(v.w);
        out[i] = v;
    }
}

// in[R][Cc] -> out[Cc][R], rounded to tf32
__global__ void transpose_round_kernel(const float* __restrict__ in,
                                       float* __restrict__ out, int R, int Cc) {
    __shared__ float tbuf[32][33];
    int c0 = blockIdx.x * 32, r0 = blockIdx.y * 32;
    int tx = threadIdx.x, ty = threadIdx.y;  // 32x8
#pragma unroll
    for (int j = 0; j < 4; j++) {
        int r = r0 + ty + j * 8, c = c0 + tx;
        tbuf[ty + j * 8][tx] = (r < R && c < Cc) ? in[(size_t)r * Cc + c] : 0.f;
    }
    __syncthreads();
#pragma unroll
    for (int j = 0; j < 4; j++) {
        int c = c0 + ty + j * 8, r = r0 + tx;
        if (c < Cc && r < R) out[(size_t)c * R + r] = rtf32(tbuf[tx][ty + j * 8]);
    }
}

// ---------------- launch ----------------------------------------------------
static inline dim3 gmk(int M, int N) {
    return dim3((unsigned)((N + 127) / 128), (unsigned)((M + 127) / 128), 1);
}

extern "C" void kernel_launch(void* const* d_in, const int* in_sizes, int n_in,
                              void* d_out, int out_size) {
    const float* x   = (const float*)d_in[0];
    const float* adj = (const float*)d_in[1];
    const float* W1  = (const float*)d_in[2];
    const float* b1  = (const float*)d_in[3];
    const float* W2  = (const float*)d_in[4];
    const float* b2  = (const float*)d_in[5];
    const float* W3  = (const float*)d_in[6];
    const float* b3  = (const float*)d_in[7];
    const float* Wf  = (const float*)d_in[8];
    const float* bf  = (const float*)d_in[9];
    float* out = (float*)d_out;

    float *bufA, *bufB, *adjr, *wts;
    cudaGetSymbolAddress((void**)&bufA, g_bufA);
    cudaGetSymbolAddress((void**)&bufB, g_bufB);
    cudaGetSymbolAddress((void**)&adjr, g_adjr);
    cudaGetSymbolAddress((void**)&wts, g_wts);

    cudaFuncSetAttribute(tc_gemm<1, 0, 0, 1>, cudaFuncAttributeMaxDynamicSharedMemorySize, SMEM_TOTAL);
    cudaFuncSetAttribute(tc_gemm<0, 1, 1, 1>, cudaFuncAttributeMaxDynamicSharedMemorySize, SMEM_TOTAL);
    cudaFuncSetAttribute(tc_gemm<0, 1, 0, 0>, cudaFuncAttributeMaxDynamicSharedMemorySize, SMEM_TOTAL);

    const int M = NNODES;

    // prep: RNA-round adj and x to tf32; transpose+round weights
    round_copy_kernel<<<4096, 256>>>((const float4*)adj, (float4*)adjr,
                                     (int)((size_t)M * M / 4));
    round_copy_kernel<<<2048, 256>>>((const float4*)x, (float4*)bufA, M * 512 / 4);
    transpose_round_kernel<<<dim3(16, 16), dim3(32, 8)>>>(W1, wts + O_W1T, 512, 512);
    transpose_round_kernel<<<dim3(16, 16), dim3(32, 8)>>>(W2, wts + O_W2T, 512, 512);
    transpose_round_kernel<<<dim3(32, 16), dim3(32, 8)>>>(W3, wts + O_W3T, 512, 1024);
    transpose_round_kernel<<<dim3(5, 32), dim3(32, 8)>>>(Wf, wts + O_WFT, 1024, 151);

    // F1: bufB = (x @ W1)^T                [512 x 10000]
    tc_gemm<1, 0, 0, 1><<<gmk(M, 512), 128, SMEM_TOTAL>>>(bufA, wts + O_W1T, nullptr, bufB, M, 512, 512);
    // G1: bufA = relu(adj @ (x@W1) + b1)   [10000 x 512]
    tc_gemm<0, 1, 1, 1><<<gmk(M, 512), 128, SMEM_TOTAL>>>(adjr, bufB, b1, bufA, M, 512, M);
    // F2
    tc_gemm<1, 0, 0, 1><<<gmk(M, 512), 128, SMEM_TOTAL>>>(bufA, wts + O_W2T, nullptr, bufB, M, 512, 512);
    // G2
    tc_gemm<0, 1, 1, 1><<<gmk(M, 512), 128, SMEM_TOTAL>>>(adjr, bufB, b2, bufA, M, 512, M);
    // F3: bufB = (H2 @ W3)^T               [1024 x 10000]
    tc_gemm<1, 0, 0, 1><<<gmk(M, 1024), 128, SMEM_TOTAL>>>(bufA, wts + O_W3T, nullptr, bufB, M, 1024, 512);
    // G3
    tc_gemm<0, 1, 1, 1><<<gmk(M, 1024), 128, SMEM_TOTAL>>>(adjr, bufB, b3, bufA, M, 1024, M);
    // F4: out = H3 @ Wf + bf               [10000 x 151]
    tc_gemm<0, 1, 0, 0><<<gmk(M, 151), 128, SMEM_TOTAL>>>(bufA, wts + O_WFT, bf, out, M, 1024 == 1024 ? 151 : 151, 1024);
}

// round 4
// speedup vs baseline: 10.9231x; 1.1556x over previous
#include <cuda_runtime.h>
#include <cstdint>

// GCN via mma.sync tf32 + ldmatrix + cp.async (arch-stable PTX; tcgen05 is
// sm_103a-gated and the harness targets base sm_103).
// R4: CTA tile 160x128 (warp tile 80x64, 4 warps), 3-stage cp.async pipeline,
// SW128 swizzle, fp32 accumulate, RNA tf32 pre-rounding.
// 160-row tiles make G512 a single wave (252 CTAs <= 296 slots @ occ 2).

#define NNODES 10000
#define KT 32
#define A_BYTES 20480               // 160 x 32 fp32
#define STAGE_BYTES 36864           // A 20KB + B 16KB
#define SMEM_TOTAL (3 * STAGE_BYTES)

__device__ float g_bufA[(size_t)NNODES * 1024];
__device__ float g_bufB[(size_t)NNODES * 1024];
__device__ float g_adjr[(size_t)NNODES * (size_t)NNODES];
__device__ float g_wts[1310720];
#define O_W1T 0
#define O_W2T 262144
#define O_W3T 524288
#define O_WFT 1048576

__device__ __forceinline__ uint32_t smem_u32(const void* p) {
    uint32_t a;
    asm("{ .reg .u64 t; cvta.to.shared.u64 t, %1; cvt.u32.u64 %0, t; }"
        : "=r"(a) : "l"(p));
    return a;
}
// round-to-nearest tf32 (add half-ulp, mask low 13 bits)
__device__ __forceinline__ float rtf32(float v) {
    return __uint_as_float((__float_as_uint(v) + 0x1000u) & 0xFFFFE000u);
}

__device__ __forceinline__ void cpa16(uint32_t dst, const float* src, int bytes) {
    asm volatile("cp.async.cg.shared.global [%0], [%1], 16, %2;"
                 :: "r"(dst), "l"(src), "r"(bytes) : "memory");
}
#define CP_COMMIT() asm volatile("cp.async.commit_group;" ::: "memory")
#define CP_WAIT1()  asm volatile("cp.async.wait_group 1;" ::: "memory")
#define CP_WAIT0()  asm volatile("cp.async.wait_group 0;" ::: "memory")

__device__ __forceinline__ void ldsm4(uint32_t* r, uint32_t a) {
    asm volatile("ldmatrix.sync.aligned.m8n8.x4.shared.b16 {%0,%1,%2,%3}, [%4];"
                 : "=r"(r[0]), "=r"(r[1]), "=r"(r[2]), "=r"(r[3]) : "r"(a));
}
__device__ __forceinline__ void ldsm2(uint32_t* r, uint32_t a) {
    asm volatile("ldmatrix.sync.aligned.m8n8.x2.shared.b16 {%0,%1}, [%2];"
                 : "=r"(r[0]), "=r"(r[1]) : "r"(a));
}
__device__ __forceinline__ void mma8(float* c, const uint32_t* a, const uint32_t* b) {
    asm volatile("mma.sync.aligned.m16n8k8.row.col.f32.tf32.tf32.f32 "
                 "{%0,%1,%2,%3}, {%4,%5,%6,%7}, {%8,%9}, {%0,%1,%2,%3};"
                 : "+f"(c[0]), "+f"(c[1]), "+f"(c[2]), "+f"(c[3])
                 : "r"(a[0]), "r"(a[1]), "r"(a[2]), "r"(a[3]),
                   "r"(b[0]), "r"(b[1]));
}

// C = A[M,K] @ B_nk[N,K]^T ; A,B row-major, leading dim K.
// TRANS: write C^T [N,M]; else C [M,N]. CTA tile 160x128.
template <int TRANS, int BIAS, int RELU, int ROUND>
__global__ void __launch_bounds__(128, 2)
tc_gemm(const float* __restrict__ A, const float* __restrict__ B,
        const float* __restrict__ bias, float* __restrict__ C,
        int M, int N, int K) {
    extern __shared__ char smem[];
    const uint32_t sb = smem_u32(smem);
    const int tid = threadIdx.x;
    const int lane = tid & 31, w = tid >> 5;
    const int warp_m = (w & 1) * 80, warp_n = (w >> 1) * 64;
    const int rowBase = blockIdx.y * 160, colBase = blockIdx.x * 128;

    // ---- loader: chunk i covers row (tid>>3)+16i, cols (tid&7)*4..+3
    const int ldr = tid >> 3;        // 0..15
    const int ldc4 = (tid & 7) * 4;  // col offset (floats)
    const uint32_t swz = (uint32_t)(((tid & 7) ^ (ldr & 7)) * 16);
    const uint32_t dstBase = (uint32_t)(ldr * 128) + swz;
    const float* aBase = A + (size_t)(rowBase + ldr) * K + ldc4;
    const float* bBase = B + (size_t)(colBase + ldr) * K + ldc4;
    const size_t K16 = (size_t)K * 16;

    const int nc = (K + KT - 1) / KT;

    auto issue = [&](int c) {
        const uint32_t st = sb + (uint32_t)(c % 3) * STAGE_BYTES;
        const int k0 = c * KT;
        const bool kok = (k0 + ldc4) < K;
#pragma unroll
        for (int i = 0; i < 10; i++) {  // A: 160 rows
            bool v = kok && (rowBase + ldr + 16 * i) < M;
            cpa16(st + dstBase + (uint32_t)i * 2048,
                  aBase + k0 + (size_t)i * K16, v ? 16 : 0);
        }
#pragma unroll
        for (int i = 0; i < 8; i++) {   // B: 128 rows
            bool v = kok && (colBase + ldr + 16 * i) < N;
            cpa16(st + A_BYTES + dstBase + (uint32_t)i * 2048,
                  bBase + k0 + (size_t)i * K16, v ? 16 : 0);
        }
        CP_COMMIT();
    };

    issue(0);
    issue(1);

    // ---- fragment addressing (SW128, ldmatrix) ----
    const int l8 = lane & 7;
    const int l16 = lane & 15;
    const uint32_t aLdRow = (uint32_t)(warp_m + l8 + ((lane >> 3) & 1) * 8) * 128;
    const uint32_t bLdRow = (uint32_t)(warp_n + (l16 & 7)) * 128;
    uint32_t aChunk[4], bChunk[4];
#pragma unroll
    for (int s = 0; s < 4; s++) {
        aChunk[s] = (uint32_t)(((s * 2 + (lane >> 4)) ^ l8) * 16);
        bChunk[s] = (uint32_t)(((s * 2 + (l16 >> 3)) ^ (l16 & 7)) * 16);
    }

    float cr[5][8][4];
#pragma unroll
    for (int mt = 0; mt < 5; mt++)
#pragma unroll
        for (int nt = 0; nt < 8; nt++)
#pragma unroll
            for (int r = 0; r < 4; r++) cr[mt][nt][r] = 0.f;

    for (int c = 0; c < nc; c++) {
        CP_WAIT1();
        __syncthreads();
        if (c + 2 < nc) issue(c + 2); else CP_COMMIT();

        const uint32_t sA = sb + (uint32_t)(c % 3) * STAGE_BYTES;
        const uint32_t sB = sA + A_BYTES;
#pragma unroll
        for (int s = 0; s < 4; s++) {
            uint32_t a[5][4], b[8][2];
#pragma unroll
            for (int mt = 0; mt < 5; mt++)
                ldsm4(a[mt], sA + aLdRow + mt * 2048 + aChunk[s]);
#pragma unroll
            for (int nt = 0; nt < 8; nt++)
                ldsm2(b[nt], sB + bLdRow + nt * 1024 + bChunk[s]);
#pragma unroll
            for (int mt = 0; mt < 5; mt++)
#pragma unroll
                for (int nt = 0; nt < 8; nt++)
                    mma8(cr[mt][nt], a[mt], b[nt]);
        }
    }
    CP_WAIT0();

    // ---- epilogue ----
    const int g = lane >> 2, t = lane & 3;
#pragma unroll
    for (int mt = 0; mt < 5; mt++) {
        const int m0 = rowBase + warp_m + mt * 16 + g;
#pragma unroll
        for (int nt = 0; nt < 8; nt++) {
            const int n0 = colBase + warp_n + nt * 8 + 2 * t;
            float v0 = cr[mt][nt][0], v1 = cr[mt][nt][1];
            float v2 = cr[mt][nt][2], v3 = cr[mt][nt][3];
            if (BIAS) {
                float bb0 = (n0 < N) ? bias[n0] : 0.f;
                float bb1 = (n0 + 1 < N) ? bias[n0 + 1] : 0.f;
                v0 += bb0; v1 += bb1; v2 += bb0; v3 += bb1;
            }
            if (RELU) {
                v0 = fmaxf(v0, 0.f); v1 = fmaxf(v1, 0.f);
                v2 = fmaxf(v2, 0.f); v3 = fmaxf(v3, 0.f);
            }
            if (ROUND) {
                v0 = rtf32(v0); v1 = rtf32(v1);
                v2 = rtf32(v2); v3 = rtf32(v3);
            }
            if (TRANS) {
                if (n0 < N) {
                    if (m0 < M)     C[(size_t)n0 * M + m0] = v0;
                    if (m0 + 8 < M) C[(size_t)n0 * M + m0 + 8] = v2;
                }
                if (n0 + 1 < N) {
                    if (m0 < M)     C[(size_t)(n0 + 1) * M + m0] = v1;
                    if (m0 + 8 < M) C[(size_t)(n0 + 1) * M + m0 + 8] = v3;
                }
            } else {
                if (m0 < M) {
                    if (n0 < N)     C[(size_t)m0 * N + n0] = v0;
                    if (n0 + 1 < N) C[(size_t)m0 * N + n0 + 1] = v1;
                }
                if (m0 + 8 < M) {
                    if (n0 < N)     C[(size_t)(m0 + 8) * N + n0] = v2;
                    if (n0 + 1 < N) C[(size_t)(m0 + 8) * N + n0 + 1] = v3;
                }
            }
        }
    }
}

// ---------------- prep kernels ---------------------------------------------
__global__ void round_copy_kernel(const float4* __restrict__ in,
                                  float4* __restrict__ out, int nquads) {
    int i = blockIdx.x * blockDim.x + threadIdx.x;
    int stride = gridDim.x * blockDim.x;
    for (; i < nquads; i += stride) {
        float4 v = in[i];
        v.x = rtf32(v.x); v.y = rtf32(v.y); v.z = rtf32(v.z); v.w = rtf32(v.w);
        out[i] = v;
    }
}

// in[R][Cc] -> out[Cc][R], rounded to tf32
__global__ void transpose_round_kernel(const float* __restrict__ in,
                                       float* __restrict__ out, int R, int Cc) {
    __shared__ float tbuf[32][33];
    int c0 = blockIdx.x * 32, r0 = blockIdx.y * 32;
    int tx = threadIdx.x, ty = threadIdx.y;  // 32x8
#pragma unroll
    for (int j = 0; j < 4; j++) {
        int r = r0 + ty + j * 8, c = c0 + tx;
        tbuf[ty + j * 8][tx] = (r < R && c < Cc) ? in[(size_t)r * Cc + c] : 0.f;
    }
    __syncthreads();
#pragma unroll
    for (int j = 0; j < 4; j++) {
        int c = c0 + ty + j * 8, r = r0 + tx;
        if (c < Cc && r < R) out[(size_t)c * R + r] = rtf32(tbuf[tx][ty + j * 8]);
    }
}

// ---------------- launch ----------------------------------------------------
static inline dim3 gmk(int M, int N) {
    return dim3((unsigned)((N + 127) / 128), (unsigned)((M + 159) / 160), 1);
}

extern "C" void kernel_launch(void* const* d_in, const int* in_sizes, int n_in,
                              void* d_out, int out_size) {
    const float* x   = (const float*)d_in[0];
    const float* adj = (const float*)d_in[1];
    const float* W1  = (const float*)d_in[2];
    const float* b1  = (const float*)d_in[3];
    const float* W2  = (const float*)d_in[4];
    const float* b2  = (const float*)d_in[5];
    const float* W3  = (const float*)d_in[6];
    const float* b3  = (const float*)d_in[7];
    const float* Wf  = (const float*)d_in[8];
    const float* bf  = (const float*)d_in[9];
    float* out = (float*)d_out;

    float *bufA, *bufB, *adjr, *wts;
    cudaGetSymbolAddress((void**)&bufA, g_bufA);
    cudaGetSymbolAddress((void**)&bufB, g_bufB);
    cudaGetSymbolAddress((void**)&adjr, g_adjr);
    cudaGetSymbolAddress((void**)&wts, g_wts);

    cudaFuncSetAttribute(tc_gemm<1, 0, 0, 1>, cudaFuncAttributeMaxDynamicSharedMemorySize, SMEM_TOTAL);
    cudaFuncSetAttribute(tc_gemm<0, 1, 1, 1>, cudaFuncAttributeMaxDynamicSharedMemorySize, SMEM_TOTAL);
    cudaFuncSetAttribute(tc_gemm<0, 1, 0, 0>, cudaFuncAttributeMaxDynamicSharedMemorySize, SMEM_TOTAL);

    const int M = NNODES;

    // prep: RNA-round adj and x to tf32; transpose+round weights
    round_copy_kernel<<<4096, 256>>>((const float4*)adj, (float4*)adjr,
                                     (int)((size_t)M * M / 4));
    round_copy_kernel<<<2048, 256>>>((const float4*)x, (float4*)bufA, M * 512 / 4);
    transpose_round_kernel<<<dim3(16, 16), dim3(32, 8)>>>(W1, wts + O_W1T, 512, 512);
    transpose_round_kernel<<<dim3(16, 16), dim3(32, 8)>>>(W2, wts + O_W2T, 512, 512);
    transpose_round_kernel<<<dim3(32, 16), dim3(32, 8)>>>(W3, wts + O_W3T, 512, 1024);
    transpose_round_kernel<<<dim3(5, 32), dim3(32, 8)>>>(Wf, wts + O_WFT, 1024, 151);

    // F1: bufB = (x @ W1)^T                [512 x 10000]
    tc_gemm<1, 0, 0, 1><<<gmk(M, 512), 128, SMEM_TOTAL>>>(bufA, wts + O_W1T, nullptr, bufB, M, 512, 512);
    // G1: bufA = relu(adj @ (x@W1) + b1)   [10000 x 512]
    tc_gemm<0, 1, 1, 1><<<gmk(M, 512), 128, SMEM_TOTAL>>>(adjr, bufB, b1, bufA, M, 512, M);
    // F2
    tc_gemm<1, 0, 0, 1><<<gmk(M, 512), 128, SMEM_TOTAL>>>(bufA, wts + O_W2T, nullptr, bufB, M, 512, 512);
    // G2
    tc_gemm<0, 1, 1, 1><<<gmk(M, 512), 128, SMEM_TOTAL>>>(adjr, bufB, b2, bufA, M, 512, M);
    // F3: bufB = (H2 @ W3)^T               [1024 x 10000]
    tc_gemm<1, 0, 0, 1><<<gmk(M, 1024), 128, SMEM_TOTAL>>>(bufA, wts + O_W3T, nullptr, bufB, M, 1024, 512);
    // G3
    tc_gemm<0, 1, 1, 1><<<gmk(M, 1024), 128, SMEM_TOTAL>>>(adjr, bufB, b3, bufA, M, 1024, M);
    // F4: out = H3 @ Wf + bf               [10000 x 151]
    tc_gemm<0, 1, 0, 0><<<gmk(M, 151), 128, SMEM_TOTAL>>>(bufA, wts + O_WFT, bf, out, M, 151, 1024);
}